// round 8
// baseline (speedup 1.0000x reference)
#include <cuda_runtime.h>
#include <cuda_bf16.h>
#include <math.h>
#include <stdint.h>

// ---------------- problem constants ----------------
#define NN 50000
#define EE 400000

// weight split buffer offsets (elements): [NC][K] row-major per GEMM
#define WOFF_S0 0
#define WOFF_D0 (WOFF_S0 + 128*256)
#define WOFF_R0 (WOFF_D0 + 128*256)
#define WOFF_S1 (WOFF_R0 + 128*256)
#define WOFF_D1 (WOFF_S1 + 256*256)
#define WOFF_S2 (WOFF_D1 + 256*256)
#define WOFF_D2 (WOFF_S2 + 256*160)
#define WOFF_R2 (WOFF_D2 + 256*160)
#define WTOT    (WOFF_R2 + 256*160)

// ---------------- scratch (static device globals; 16B-aligned for cp.async) ----------------
__device__ float g_hs[NN * 256];
__device__ float g_hd[NN * 256];
__device__ float g_res[NN * 256];
__device__ float g_xA[NN * 256];
__device__ __align__(256) __nv_bfloat16 g_xhi[NN * 256];
__device__ __align__(256) __nv_bfloat16 g_xlo[NN * 256];
__device__ __align__(256) __nv_bfloat16 g_whi[WTOT];
__device__ __align__(256) __nv_bfloat16 g_wlo[WTOT];
__device__ int   g_deg[NN];
__device__ int   g_cur[NN];
__device__ int   g_off[NN + 1];
__device__ int   g_ssrc[EE];
__device__ int   g_bsum[64];

// ---------------- helpers ----------------
__device__ __forceinline__ uint32_t smem_to_u32(const void* p) {
    uint32_t a;
    asm("{ .reg .u64 t; cvta.to.shared.u64 t, %1; cvt.u32.u64 %0, t; }" : "=r"(a) : "l"(p));
    return a;
}
__device__ __forceinline__ void cp16(uint32_t saddr, const void* gaddr, int sz) {
    asm volatile("cp.async.cg.shared.global [%0], [%1], 16, %2;\n"
                 :: "r"(saddr), "l"(gaddr), "r"(sz));
}
__device__ __forceinline__ void cp_commit() {
    asm volatile("cp.async.commit_group;\n" ::: "memory");
}
template<int N> __device__ __forceinline__ void cp_wait() {
    asm volatile("cp.async.wait_group %0;\n" :: "n"(N) : "memory");
}
__device__ __forceinline__ void ldsm4(uint32_t* r, uint32_t addr) {
    asm volatile("ldmatrix.sync.aligned.m8n8.x4.shared.b16 {%0,%1,%2,%3}, [%4];"
                 : "=r"(r[0]), "=r"(r[1]), "=r"(r[2]), "=r"(r[3]) : "r"(addr));
}
__device__ __forceinline__ void ldsm2(uint32_t* r, uint32_t addr) {
    asm volatile("ldmatrix.sync.aligned.m8n8.x2.shared.b16 {%0,%1}, [%2];"
                 : "=r"(r[0]), "=r"(r[1]) : "r"(addr));
}
__device__ __forceinline__ void mma_bf16(float* c, const uint32_t* a, uint32_t b0, uint32_t b1) {
    asm volatile(
        "mma.sync.aligned.m16n8k16.row.col.f32.bf16.bf16.f32 "
        "{%0,%1,%2,%3}, {%4,%5,%6,%7}, {%8,%9}, {%0,%1,%2,%3};\n"
        : "+f"(c[0]), "+f"(c[1]), "+f"(c[2]), "+f"(c[3])
        : "r"(a[0]), "r"(a[1]), "r"(a[2]), "r"(a[3]), "r"(b0), "r"(b1));
}

// ---------------- CSR build ----------------
__global__ void k_zero(int n) {
    int i = blockIdx.x * 256 + threadIdx.x;
    if (i < n) { g_deg[i] = 0; g_cur[i] = 0; }
}
__global__ void k_hist(const int* __restrict__ dst, int E) {
    int i = blockIdx.x * 256 + threadIdx.x;
    if (i < E) atomicAdd(&g_deg[dst[i]], 1);
}
__global__ void k_scan_reduce(int n) {
    __shared__ int sm[1024];
    int tid = threadIdx.x;
    int i = blockIdx.x * 1024 + tid;
    sm[tid] = (i < n) ? g_deg[i] : 0;
    __syncthreads();
    for (int st = 512; st > 0; st >>= 1) {
        if (tid < st) sm[tid] += sm[tid + st];
        __syncthreads();
    }
    if (tid == 0) g_bsum[blockIdx.x] = sm[0];
}
__global__ void k_scan_bsum(int nb, int n, int E) {
    int run = 0;
    for (int b = 0; b < nb; b++) { int t = g_bsum[b]; g_bsum[b] = run; run += t; }
    g_off[n] = E;
}
__global__ void k_scan_final(int n) {
    __shared__ int sm[1024];
    int tid = threadIdx.x;
    int i = blockIdx.x * 1024 + tid;
    int v = (i < n) ? g_deg[i] : 0;
    sm[tid] = v;
    __syncthreads();
    for (int st = 1; st < 1024; st <<= 1) {
        int t = (tid >= st) ? sm[tid - st] : 0;
        __syncthreads();
        sm[tid] += t;
        __syncthreads();
    }
    if (i < n) g_off[i] = g_bsum[blockIdx.x] + sm[tid] - v;
}
__global__ void k_scatter(const int* __restrict__ src, const int* __restrict__ dst, int E) {
    int i = blockIdx.x * 256 + threadIdx.x;
    if (i < E) {
        int d = dst[i];
        int p = g_off[d] + atomicAdd(&g_cur[d], 1);
        g_ssrc[p] = src[i];
    }
}

// ---------------- split / transpose prep ----------------
__global__ void k_xsplit(const float* __restrict__ X,
                         __nv_bfloat16* __restrict__ hi, __nv_bfloat16* __restrict__ lo, int n)
{
    int i = blockIdx.x * 256 + threadIdx.x;
    if (i < n) {
        float v = X[i];
        __nv_bfloat16 h = __float2bfloat16(v);
        hi[i] = h;
        lo[i] = __float2bfloat16(v - __bfloat162float(h));
    }
}
// W[K,NC] -> W'[n][k] = W[k][n], split hi/lo, row-major [NC][K] at offset woff.
__global__ void k_wsplit(const float* __restrict__ W, int K, int NC, int woff)
{
    int i = blockIdx.x * 256 + threadIdx.x;
    if (i < K * NC) {
        int n = i / K, k = i - n * K;
        float v = W[(size_t)k * NC + n];
        __nv_bfloat16 h = __float2bfloat16(v);
        g_whi[woff + i] = h;
        g_wlo[woff + i] = __float2bfloat16(v - __bfloat162float(h));
    }
}

// ---------------- bf16x3 mma.sync GEMM, cp.async + ldmatrix, 16 warps ----------------
// C[M,NC] = X @ W + bias via D += Ahi*Bhi + Ahi*Blo + Alo*Bhi.
// BM=128, BN=NFRAG*32 (128 or 160), BK=32, 512 threads: 4x4 warp grid,
// warp tile 32 x NFRAG*8. SMEM rows 40 bf16 (80B) -> conflict-free LDSM.
template<int NFRAG>
__global__ void __launch_bounds__(512, 1) gemm_bf16x3(
    const __nv_bfloat16* __restrict__ Ahi, const __nv_bfloat16* __restrict__ Alo,
    const __nv_bfloat16* __restrict__ WhiBase, const __nv_bfloat16* __restrict__ WloBase,
    int woff, const float* __restrict__ bias, float* __restrict__ C,
    int M, int K, int NC)
{
    extern __shared__ char smem[];
    constexpr int BN = NFRAG * 32;
    constexpr int szA = 128 * 80;
    constexpr int szB = BN * 80;
    constexpr int stageSz = 2 * szA + 2 * szB;
    constexpr int NP = NFRAG / 2;      // x4 B-pairs

    const uint32_t sb = smem_to_u32(smem);
    const int tid  = threadIdx.x;
    const int lane = tid & 31;
    const int wid  = tid >> 5;
    const int wr   = (wid & 3) * 32;           // warp row base
    const int wc   = (wid >> 2) * (NFRAG * 8); // warp col base
    const int bm   = blockIdx.x * 128;
    const int bn   = blockIdx.y * 128;
    const int g    = lane >> 2;
    const int tg   = lane & 3;
    const int m8   = lane >> 3;                // ldmatrix sub-matrix id
    const int r8   = lane & 7;
    // ldmatrix lane->address components
    const int aRow = (m8 & 1) * 8 + r8;        // A: m0/m2 rows+0, m1/m3 rows+8
    const int aK   = (m8 >> 1) * 16;           // A: m2/m3 k+8 (16B)
    const int bRow = (m8 >> 1) * 8 + r8;       // B: m2/m3 n+8
    const int bK   = (m8 & 1) * 16;            // B: m1/m3 k+8
    const __nv_bfloat16* __restrict__ Bhi = WhiBase + woff;
    const __nv_bfloat16* __restrict__ Blo = WloBase + woff;

    float acc[2][NFRAG][4];
#pragma unroll
    for (int i = 0; i < 2; i++)
#pragma unroll
        for (int j = 0; j < NFRAG; j++)
#pragma unroll
            for (int k = 0; k < 4; k++) acc[i][j][k] = 0.f;

    auto stage = [&](int s, int kofs) {
        uint32_t base = sb + s * stageSz;
        // A hi+lo: 128 rows x 4 chunks = 512 items (one per thread)
        {
            int row = tid >> 2, c = tid & 3;
            uint32_t sa = base + row * 80 + c * 16;
            size_t go = (size_t)(bm + row) * K + kofs + c * 8;
            int sz = (bm + row < M) ? 16 : 0;
            cp16(sa, Ahi + go, sz);
            cp16(sa + szA, Alo + go, sz);
        }
        // B hi+lo: BN rows x 4 chunks
        for (int i = tid; i < BN * 4; i += 512) {
            int row = i >> 2, c = i & 3;
            uint32_t sa = base + 2 * szA + row * 80 + c * 16;
            size_t go = (size_t)(bn + row) * K + kofs + c * 8;
            cp16(sa, Bhi + go, 16);
            cp16(sa + szB, Blo + go, 16);
        }
    };

    stage(0, 0);
    cp_commit();

    const int NKT = K >> 5;
    for (int kt = 0; kt < NKT; kt++) {
        if (kt + 1 < NKT) {
            stage((kt + 1) & 1, (kt + 1) * 32);
            cp_commit();
            cp_wait<1>();
        } else {
            cp_wait<0>();
        }
        __syncthreads();

        const uint32_t sAh = sb + (kt & 1) * stageSz;
        const uint32_t sAl = sAh + szA;
        const uint32_t sBh = sAh + 2 * szA;
        const uint32_t sBl = sBh + szB;
#pragma unroll
        for (int kc = 0; kc < 2; kc++) {
            const int kb = kc * 32;
            uint32_t ah[2][4], al[2][4];
#pragma unroll
            for (int fr = 0; fr < 2; fr++) {
                uint32_t off = (uint32_t)(wr + fr * 16 + aRow) * 80 + kb + aK;
                ldsm4(ah[fr], sAh + off);
                ldsm4(al[fr], sAl + off);
            }
            uint32_t bh[NFRAG][2], bl[NFRAG][2];
#pragma unroll
            for (int p = 0; p < NP; p++) {
                uint32_t off = (uint32_t)(wc + p * 16 + bRow) * 80 + kb + bK;
                uint32_t t[4];
                ldsm4(t, sBh + off);
                bh[2*p][0] = t[0]; bh[2*p][1] = t[1]; bh[2*p+1][0] = t[2]; bh[2*p+1][1] = t[3];
                ldsm4(t, sBl + off);
                bl[2*p][0] = t[0]; bl[2*p][1] = t[1]; bl[2*p+1][0] = t[2]; bl[2*p+1][1] = t[3];
            }
            if (NFRAG & 1) {
                // last fc via x2 (lanes 0-15 give rows; m8&1 selects k half)
                uint32_t off = (uint32_t)(wc + (NFRAG - 1) * 8 + r8) * 80 + kb + (m8 & 1) * 16;
                uint32_t t[2];
                ldsm2(t, sBh + off);
                bh[NFRAG-1][0] = t[0]; bh[NFRAG-1][1] = t[1];
                ldsm2(t, sBl + off);
                bl[NFRAG-1][0] = t[0]; bl[NFRAG-1][1] = t[1];
            }
#pragma unroll
            for (int fc = 0; fc < NFRAG; fc++)
#pragma unroll
                for (int fr = 0; fr < 2; fr++) {
                    mma_bf16(acc[fr][fc], ah[fr], bh[fc][0], bh[fc][1]);
                    mma_bf16(acc[fr][fc], ah[fr], bl[fc][0], bl[fc][1]);
                    mma_bf16(acc[fr][fc], al[fr], bh[fc][0], bh[fc][1]);
                }
        }
        __syncthreads();
    }

    // epilogue: bias + float2 stores (C-frag rows g, g+8; cols 2tg, 2tg+1)
#pragma unroll
    for (int fr = 0; fr < 2; fr++) {
        int r0 = bm + wr + fr * 16 + g;
#pragma unroll
        for (int fc = 0; fc < NFRAG; fc++) {
            int c = bn + wc + fc * 8 + tg * 2;
            float2 bb = *(const float2*)(bias + c);
            if (r0 < M) {
                float2 o = make_float2(acc[fr][fc][0] + bb.x, acc[fr][fc][1] + bb.y);
                *(float2*)(C + (size_t)r0 * NC + c) = o;
            }
            if (r0 + 8 < M) {
                float2 o = make_float2(acc[fr][fc][2] + bb.x, acc[fr][fc][3] + bb.y);
                *(float2*)(C + (size_t)(r0 + 8) * NC + c) = o;
            }
        }
    }
}

// ---------------- edge kernels (warp per dst node, online softmax, 1-edge prefetch) ----------------
__device__ __forceinline__ float lrelu(float t) { return t > 0.f ? t : 0.2f * t; }
__device__ __forceinline__ float lrdot(float4 h, float4 d, float4 a) {
    return lrelu(h.x + d.x) * a.x + lrelu(h.y + d.y) * a.y +
           lrelu(h.z + d.z) * a.z + lrelu(h.w + d.w) * a.w;
}

__global__ void __launch_bounds__(256) gat_edge_d64(
    const float* __restrict__ hs, const float* __restrict__ hd,
    const float* __restrict__ attn, const float* __restrict__ res,
    float* __restrict__ xout,
    __nv_bfloat16* __restrict__ xhi, __nv_bfloat16* __restrict__ xlo, int N)
{
    int w = (blockIdx.x * blockDim.x + threadIdx.x) >> 5;
    if (w >= N) return;
    int lane = threadIdx.x & 31;
    int i1 = 4 * lane, i2 = 128 + 4 * lane;
    size_t nb = (size_t)w * 256;
    float4 a1 = *(const float4*)(attn + i1);
    float4 a2 = *(const float4*)(attn + i2);
    float4 d1 = *(const float4*)(hd + nb + i1);
    float4 d2 = *(const float4*)(hd + nb + i2);
    float m1 = -1e30f, s1 = 0.f, m2 = -1e30f, s2 = 0.f;
    float4 c1 = make_float4(0.f, 0.f, 0.f, 0.f);
    float4 c2 = make_float4(0.f, 0.f, 0.f, 0.f);
    int e0 = g_off[w], e1 = g_off[w + 1];
    float4 h1c, h2c;
    if (e0 < e1) {
        const float* hp = hs + (size_t)g_ssrc[e0] * 256;
        h1c = *(const float4*)(hp + i1);
        h2c = *(const float4*)(hp + i2);
    }
    for (int e = e0; e < e1; e++) {
        float4 h1 = h1c, h2 = h2c;
        if (e + 1 < e1) {
            const float* hp = hs + (size_t)g_ssrc[e + 1] * 256;
            h1c = *(const float4*)(hp + i1);
            h2c = *(const float4*)(hp + i2);
        }
        float p1 = lrdot(h1, d1, a1);
        float p2 = lrdot(h2, d2, a2);
#pragma unroll
        for (int o = 8; o; o >>= 1) {
            p1 += __shfl_xor_sync(0xffffffffu, p1, o);
            p2 += __shfl_xor_sync(0xffffffffu, p2, o);
        }
        float nm = fmaxf(m1, p1);
        float sc = __expf(m1 - nm), wt = __expf(p1 - nm);
        s1 = s1 * sc + wt;
        c1.x = c1.x * sc + wt * h1.x; c1.y = c1.y * sc + wt * h1.y;
        c1.z = c1.z * sc + wt * h1.z; c1.w = c1.w * sc + wt * h1.w;
        m1 = nm;
        nm = fmaxf(m2, p2);
        sc = __expf(m2 - nm); wt = __expf(p2 - nm);
        s2 = s2 * sc + wt;
        c2.x = c2.x * sc + wt * h2.x; c2.y = c2.y * sc + wt * h2.y;
        c2.z = c2.z * sc + wt * h2.z; c2.w = c2.w * sc + wt * h2.w;
        m2 = nm;
    }
    float v1 = (s1 > 0.f) ? 1.f / s1 : 0.f;
    float v2 = (s2 > 0.f) ? 1.f / s2 : 0.f;
    float4 r1 = *(const float4*)(res + nb + i1);
    float4 r2 = *(const float4*)(res + nb + i2);
    float o1[4], o2[4];
    o1[0] = c1.x * v1 + r1.x; o1[1] = c1.y * v1 + r1.y;
    o1[2] = c1.z * v1 + r1.z; o1[3] = c1.w * v1 + r1.w;
    o2[0] = c2.x * v2 + r2.x; o2[1] = c2.y * v2 + r2.y;
    o2[2] = c2.z * v2 + r2.z; o2[3] = c2.w * v2 + r2.w;
    if (xout) {
        *(float4*)(xout + nb + i1) = make_float4(o1[0], o1[1], o1[2], o1[3]);
        *(float4*)(xout + nb + i2) = make_float4(o2[0], o2[1], o2[2], o2[3]);
    }
#pragma unroll
    for (int j = 0; j < 4; j++) {
        __nv_bfloat16 h = __float2bfloat16(o1[j]);
        xhi[nb + i1 + j] = h;
        xlo[nb + i1 + j] = __float2bfloat16(o1[j] - __bfloat162float(h));
        h = __float2bfloat16(o2[j]);
        xhi[nb + i2 + j] = h;
        xlo[nb + i2 + j] = __float2bfloat16(o2[j] - __bfloat162float(h));
    }
}

__global__ void __launch_bounds__(256) gat_edge_d40(
    const float* __restrict__ hs, const float* __restrict__ hd,
    const float* __restrict__ attn, const float* __restrict__ res,
    float* __restrict__ out, int N)
{
    int w = (blockIdx.x * blockDim.x + threadIdx.x) >> 5;
    if (w >= N) return;
    int lane = threadIdx.x & 31;
    int h = lane >> 3;
    int d0 = (lane & 7) * 5;
    int idx = h * 40 + d0;
    float a[5], dv[5];
#pragma unroll
    for (int j = 0; j < 5; j++) {
        a[j] = attn[idx + j];
        dv[j] = hd[(size_t)w * 160 + idx + j];
    }
    float m = -1e30f, s = 0.f;
    float acc[5] = {0.f, 0.f, 0.f, 0.f, 0.f};
    int e0 = g_off[w], e1 = g_off[w + 1];
    float hc[5];
    if (e0 < e1) {
        const float* hp = hs + (size_t)g_ssrc[e0] * 160 + idx;
#pragma unroll
        for (int j = 0; j < 5; j++) hc[j] = hp[j];
    }
    for (int e = e0; e < e1; e++) {
        float hv[5];
#pragma unroll
        for (int j = 0; j < 5; j++) hv[j] = hc[j];
        if (e + 1 < e1) {
            const float* hp = hs + (size_t)g_ssrc[e + 1] * 160 + idx;
#pragma unroll
            for (int j = 0; j < 5; j++) hc[j] = hp[j];
        }
        float p = 0.f;
#pragma unroll
        for (int j = 0; j < 5; j++) p += lrelu(hv[j] + dv[j]) * a[j];
#pragma unroll
        for (int o = 4; o; o >>= 1) p += __shfl_xor_sync(0xffffffffu, p, o);
        float nm = fmaxf(m, p);
        float sc = __expf(m - nm), wt = __expf(p - nm);
        s = s * sc + wt;
#pragma unroll
        for (int j = 0; j < 5; j++) acc[j] = acc[j] * sc + wt * hv[j];
        m = nm;
    }
    float inv = (s > 0.f) ? 1.f / s : 0.f;
    float v[5];
#pragma unroll
    for (int j = 0; j < 5; j++) v[j] = acc[j] * inv + res[(size_t)w * 160 + idx + j];
#pragma unroll
    for (int j = 0; j < 5; j++) {
        v[j] += __shfl_xor_sync(0xffffffffu, v[j], 8);
        v[j] += __shfl_xor_sync(0xffffffffu, v[j], 16);
    }
    if (lane < 8) {
#pragma unroll
        for (int j = 0; j < 5; j++) out[(size_t)w * 40 + d0 + j] = 0.25f * v[j];
    }
}

// ---------------- launch ----------------
#define SMEM_G4 (2 * (2 * 128 * 80 + 2 * 128 * 80))   // 81920
#define SMEM_G5 (2 * (2 * 128 * 80 + 2 * 160 * 80))   // 92160

extern "C" void kernel_launch(void* const* d_in, const int* in_sizes, int n_in,
                              void* d_out, int out_size)
{
    const float* x0  = (const float*)d_in[0];
    const int*   src = (const int*)d_in[1];
    const int*   dst = (const int*)d_in[2];
    const float* ws0 = (const float*)d_in[3];
    const float* bs0 = (const float*)d_in[4];
    const float* wd0 = (const float*)d_in[5];
    const float* bd0 = (const float*)d_in[6];
    const float* at0 = (const float*)d_in[7];
    const float* wr0 = (const float*)d_in[8];
    const float* br0 = (const float*)d_in[9];
    const float* ws1 = (const float*)d_in[10];
    const float* bs1 = (const float*)d_in[11];
    const float* wd1 = (const float*)d_in[12];
    const float* bd1 = (const float*)d_in[13];
    const float* at1 = (const float*)d_in[14];
    const float* ws2 = (const float*)d_in[15];
    const float* bs2 = (const float*)d_in[16];
    const float* wd2 = (const float*)d_in[17];
    const float* bd2 = (const float*)d_in[18];
    const float* at2 = (const float*)d_in[19];
    const float* wr2 = (const float*)d_in[20];
    const float* br2 = (const float*)d_in[21];
    float* out = (float*)d_out;

    const int N = NN, E = EE;

    float *hs, *hd, *res, *xA;
    __nv_bfloat16 *xhi, *xlo, *whi, *wlo;
    cudaGetSymbolAddress((void**)&hs,  g_hs);
    cudaGetSymbolAddress((void**)&hd,  g_hd);
    cudaGetSymbolAddress((void**)&res, g_res);
    cudaGetSymbolAddress((void**)&xA,  g_xA);
    cudaGetSymbolAddress((void**)&xhi, g_xhi);
    cudaGetSymbolAddress((void**)&xlo, g_xlo);
    cudaGetSymbolAddress((void**)&whi, g_whi);
    cudaGetSymbolAddress((void**)&wlo, g_wlo);

    cudaFuncSetAttribute(gemm_bf16x3<4>, cudaFuncAttributeMaxDynamicSharedMemorySize, SMEM_G4);
    cudaFuncSetAttribute(gemm_bf16x3<5>, cudaFuncAttributeMaxDynamicSharedMemorySize, SMEM_G5);

    const int MB = (N + 127) / 128;
    const int ewarps = (N * 32 + 255) / 256;
    const dim3 g2(MB, 2);

    // ---- layer 0 prep + GEMMs first (so ncu -s 5 -c 1 lands on a GEMM) ----
    k_xsplit<<<(N * 128 + 255) / 256, 256>>>(x0, xhi, xlo, N * 128);
    k_wsplit<<<(128 * 256 + 255) / 256, 256>>>(ws0, 128, 256, WOFF_S0);
    k_wsplit<<<(128 * 256 + 255) / 256, 256>>>(wd0, 128, 256, WOFF_D0);
    gemm_bf16x3<4><<<g2, 512, SMEM_G4>>>(xhi, xlo, whi, wlo, WOFF_S0, bs0, hs, N, 128, 256);
    gemm_bf16x3<4><<<g2, 512, SMEM_G4>>>(xhi, xlo, whi, wlo, WOFF_D0, bd0, hd, N, 128, 256);
    k_wsplit<<<(128 * 256 + 255) / 256, 256>>>(wr0, 128, 256, WOFF_R0);
    gemm_bf16x3<4><<<g2, 512, SMEM_G4>>>(xhi, xlo, whi, wlo, WOFF_R0, br0, res, N, 128, 256);

    // ---- CSR by dst (needed before first edge kernel) ----
    k_zero<<<(N + 255) / 256, 256>>>(N);
    k_hist<<<(E + 255) / 256, 256>>>(dst, E);
    int NB = (N + 1023) / 1024;
    k_scan_reduce<<<NB, 1024>>>(N);
    k_scan_bsum<<<1, 1>>>(NB, N, E);
    k_scan_final<<<NB, 1024>>>(N);
    k_scatter<<<(E + 255) / 256, 256>>>(src, dst, E);

    gat_edge_d64<<<ewarps, 256>>>(hs, hd, at0, res, xA, xhi, xlo, N);

    // ---- layer 1: K=256, NC=256, identity residual ----
    k_wsplit<<<(256 * 256 + 255) / 256, 256>>>(ws1, 256, 256, WOFF_S1);
    k_wsplit<<<(256 * 256 + 255) / 256, 256>>>(wd1, 256, 256, WOFF_D1);
    gemm_bf16x3<4><<<g2, 512, SMEM_G4>>>(xhi, xlo, whi, wlo, WOFF_S1, bs1, hs, N, 256, 256);
    gemm_bf16x3<4><<<g2, 512, SMEM_G4>>>(xhi, xlo, whi, wlo, WOFF_D1, bd1, hd, N, 256, 256);
    gat_edge_d64<<<ewarps, 256>>>(hs, hd, at1, xA, nullptr, xhi, xlo, N);

    // ---- layer 2: K=256, NC=160 (BN=160, no padding), fused head-mean ----
    k_wsplit<<<(256 * 160 + 255) / 256, 256>>>(ws2, 256, 160, WOFF_S2);
    k_wsplit<<<(256 * 160 + 255) / 256, 256>>>(wd2, 256, 160, WOFF_D2);
    k_wsplit<<<(256 * 160 + 255) / 256, 256>>>(wr2, 256, 160, WOFF_R2);
    gemm_bf16x3<5><<<MB, 512, SMEM_G5>>>(xhi, xlo, whi, wlo, WOFF_S2, bs2, hs, N, 256, 160);
    gemm_bf16x3<5><<<MB, 512, SMEM_G5>>>(xhi, xlo, whi, wlo, WOFF_D2, bd2, hd, N, 256, 160);
    gemm_bf16x3<5><<<MB, 512, SMEM_G5>>>(xhi, xlo, whi, wlo, WOFF_R2, br2, res, N, 256, 160);
    gat_edge_d40<<<ewarps, 256>>>(hs, hd, at2, res, out, N);
}

// round 9
// speedup vs baseline: 1.4219x; 1.4219x over previous
#include <cuda_runtime.h>
#include <cuda_fp16.h>
#include <math.h>
#include <stdint.h>

// ---------------- problem constants ----------------
#define NN 50000
#define EE 400000

// weight buffer offsets (elements): [NC][K] row-major per GEMM
#define WOFF_S0 0
#define WOFF_D0 (WOFF_S0 + 128*256)
#define WOFF_R0 (WOFF_D0 + 128*256)
#define WOFF_S1 (WOFF_R0 + 128*256)
#define WOFF_D1 (WOFF_S1 + 256*256)
#define WOFF_S2 (WOFF_D1 + 256*256)
#define WOFF_D2 (WOFF_S2 + 256*160)
#define WOFF_R2 (WOFF_D2 + 256*160)
#define WTOT    (WOFF_R2 + 256*160)

// ---------------- scratch (static device globals; 16B-aligned for cp.async) ----------------
__device__ float g_hs[NN * 256];
__device__ float g_hd[NN * 256];
__device__ float g_res[NN * 256];
__device__ float g_xA[NN * 256];
__device__ __align__(256) __half g_xh[NN * 256];
__device__ __align__(256) __half g_wh[WTOT];
__device__ int   g_deg[NN];
__device__ int   g_cur[NN];
__device__ int   g_off[NN + 1];
__device__ int   g_ssrc[EE];
__device__ int   g_bsum[64];

// ---------------- helpers ----------------
__device__ __forceinline__ uint32_t smem_to_u32(const void* p) {
    uint32_t a;
    asm("{ .reg .u64 t; cvta.to.shared.u64 t, %1; cvt.u32.u64 %0, t; }" : "=r"(a) : "l"(p));
    return a;
}
__device__ __forceinline__ void cp16(uint32_t saddr, const void* gaddr, int sz) {
    asm volatile("cp.async.cg.shared.global [%0], [%1], 16, %2;\n"
                 :: "r"(saddr), "l"(gaddr), "r"(sz));
}
__device__ __forceinline__ void cp_commit() {
    asm volatile("cp.async.commit_group;\n" ::: "memory");
}
template<int N> __device__ __forceinline__ void cp_wait() {
    asm volatile("cp.async.wait_group %0;\n" :: "n"(N) : "memory");
}
__device__ __forceinline__ void ldsm4(uint32_t* r, uint32_t addr) {
    asm volatile("ldmatrix.sync.aligned.m8n8.x4.shared.b16 {%0,%1,%2,%3}, [%4];"
                 : "=r"(r[0]), "=r"(r[1]), "=r"(r[2]), "=r"(r[3]) : "r"(addr));
}
__device__ __forceinline__ void ldsm2(uint32_t* r, uint32_t addr) {
    asm volatile("ldmatrix.sync.aligned.m8n8.x2.shared.b16 {%0,%1}, [%2];"
                 : "=r"(r[0]), "=r"(r[1]) : "r"(addr));
}
__device__ __forceinline__ void mma_f16(float* c, const uint32_t* a, uint32_t b0, uint32_t b1) {
    asm volatile(
        "mma.sync.aligned.m16n8k16.row.col.f32.f16.f16.f32 "
        "{%0,%1,%2,%3}, {%4,%5,%6,%7}, {%8,%9}, {%0,%1,%2,%3};\n"
        : "+f"(c[0]), "+f"(c[1]), "+f"(c[2]), "+f"(c[3])
        : "r"(a[0]), "r"(a[1]), "r"(a[2]), "r"(a[3]), "r"(b0), "r"(b1));
}

// ---------------- CSR build ----------------
__global__ void k_zero(int n) {
    int i = blockIdx.x * 256 + threadIdx.x;
    if (i < n) { g_deg[i] = 0; g_cur[i] = 0; }
}
__global__ void k_hist(const int* __restrict__ dst, int E) {
    int i = blockIdx.x * 256 + threadIdx.x;
    if (i < E) atomicAdd(&g_deg[dst[i]], 1);
}
__global__ void k_scan_reduce(int n) {
    __shared__ int sm[1024];
    int tid = threadIdx.x;
    int i = blockIdx.x * 1024 + tid;
    sm[tid] = (i < n) ? g_deg[i] : 0;
    __syncthreads();
    for (int st = 512; st > 0; st >>= 1) {
        if (tid < st) sm[tid] += sm[tid + st];
        __syncthreads();
    }
    if (tid == 0) g_bsum[blockIdx.x] = sm[0];
}
__global__ void k_scan_bsum(int nb, int n, int E) {
    int run = 0;
    for (int b = 0; b < nb; b++) { int t = g_bsum[b]; g_bsum[b] = run; run += t; }
    g_off[n] = E;
}
__global__ void k_scan_final(int n) {
    __shared__ int sm[1024];
    int tid = threadIdx.x;
    int i = blockIdx.x * 1024 + tid;
    int v = (i < n) ? g_deg[i] : 0;
    sm[tid] = v;
    __syncthreads();
    for (int st = 1; st < 1024; st <<= 1) {
        int t = (tid >= st) ? sm[tid - st] : 0;
        __syncthreads();
        sm[tid] += t;
        __syncthreads();
    }
    if (i < n) g_off[i] = g_bsum[blockIdx.x] + sm[tid] - v;
}
__global__ void k_scatter(const int* __restrict__ src, const int* __restrict__ dst, int E) {
    int i = blockIdx.x * 256 + threadIdx.x;
    if (i < E) {
        int d = dst[i];
        int p = g_off[d] + atomicAdd(&g_cur[d], 1);
        g_ssrc[p] = src[i];
    }
}

// ---------------- convert / transpose prep ----------------
__global__ void k_xcvt(const float* __restrict__ X, __half* __restrict__ xh, int n)
{
    int i = blockIdx.x * 256 + threadIdx.x;
    if (i < n) xh[i] = __float2half(X[i]);
}
// W[K,NC] -> W'[n][k] = W[k][n] as fp16, row-major [NC][K] at offset woff.
__global__ void k_wcvt(const float* __restrict__ W, int K, int NC, int woff)
{
    int i = blockIdx.x * 256 + threadIdx.x;
    if (i < K * NC) {
        int n = i / K, k = i - n * K;
        g_wh[woff + i] = __float2half(W[(size_t)k * NC + n]);
    }
}

// ---------------- fp16 mma.sync GEMM, cp.async + ldmatrix, 16 warps ----------------
// C[M,NC] = X @ W + bias, single-pass fp16 (f32 accumulate).
// BM=128, BN=NFRAG*32 (128 or 160), BK=32, 512 threads: 4x4 warp grid,
// warp tile 32 x NFRAG*8. SMEM rows 40 halfs (80B) -> conflict-free LDSM.
template<int NFRAG>
__global__ void __launch_bounds__(512, 1) gemm_f16(
    const __half* __restrict__ A,
    const __half* __restrict__ WBase, int woff,
    const float* __restrict__ bias, float* __restrict__ C,
    int M, int K, int NC)
{
    extern __shared__ char smem[];
    constexpr int BN = NFRAG * 32;
    constexpr int szA = 128 * 80;
    constexpr int szB = BN * 80;
    constexpr int stageSz = szA + szB;
    constexpr int NP = NFRAG / 2;

    const uint32_t sb = smem_to_u32(smem);
    const int tid  = threadIdx.x;
    const int lane = tid & 31;
    const int wid  = tid >> 5;
    const int wr   = (wid & 3) * 32;
    const int wc   = (wid >> 2) * (NFRAG * 8);
    const int bm   = blockIdx.x * 128;
    const int bn   = blockIdx.y * 128;
    const int g    = lane >> 2;
    const int tg   = lane & 3;
    const int m8   = lane >> 3;
    const int r8   = lane & 7;
    const int aRow = (m8 & 1) * 8 + r8;
    const int aK   = (m8 >> 1) * 16;
    const int bRow = (m8 >> 1) * 8 + r8;
    const int bK   = (m8 & 1) * 16;
    const __half* __restrict__ B = WBase + woff;

    float acc[2][NFRAG][4];
#pragma unroll
    for (int i = 0; i < 2; i++)
#pragma unroll
        for (int j = 0; j < NFRAG; j++)
#pragma unroll
            for (int k = 0; k < 4; k++) acc[i][j][k] = 0.f;

    auto stage = [&](int s, int kofs) {
        uint32_t base = sb + s * stageSz;
        // A: 128 rows x 4 chunks = 512 (one per thread)
        {
            int row = tid >> 2, c = tid & 3;
            uint32_t sa = base + row * 80 + c * 16;
            size_t go = (size_t)(bm + row) * K + kofs + c * 8;
            cp16(sa, A + go, (bm + row < M) ? 16 : 0);
        }
        // B: BN rows x 4 chunks
        for (int i = tid; i < BN * 4; i += 512) {
            int row = i >> 2, c = i & 3;
            uint32_t sa = base + szA + row * 80 + c * 16;
            size_t go = (size_t)(bn + row) * K + kofs + c * 8;
            cp16(sa, B + go, 16);
        }
    };

    stage(0, 0);
    cp_commit();

    const int NKT = K >> 5;
    for (int kt = 0; kt < NKT; kt++) {
        if (kt + 1 < NKT) {
            stage((kt + 1) & 1, (kt + 1) * 32);
            cp_commit();
            cp_wait<1>();
        } else {
            cp_wait<0>();
        }
        __syncthreads();

        const uint32_t sA = sb + (kt & 1) * stageSz;
        const uint32_t sB = sA + szA;
#pragma unroll
        for (int kc = 0; kc < 2; kc++) {
            const int kb = kc * 32;
            uint32_t a[2][4];
#pragma unroll
            for (int fr = 0; fr < 2; fr++) {
                uint32_t off = (uint32_t)(wr + fr * 16 + aRow) * 80 + kb + aK;
                ldsm4(a[fr], sA + off);
            }
            uint32_t b[NFRAG][2];
#pragma unroll
            for (int p = 0; p < NP; p++) {
                uint32_t off = (uint32_t)(wc + p * 16 + bRow) * 80 + kb + bK;
                uint32_t t[4];
                ldsm4(t, sB + off);
                b[2*p][0] = t[0]; b[2*p][1] = t[1]; b[2*p+1][0] = t[2]; b[2*p+1][1] = t[3];
            }
            if (NFRAG & 1) {
                uint32_t off = (uint32_t)(wc + (NFRAG - 1) * 8 + r8) * 80 + kb + (m8 & 1) * 16;
                uint32_t t[2];
                ldsm2(t, sB + off);
                b[NFRAG-1][0] = t[0]; b[NFRAG-1][1] = t[1];
            }
#pragma unroll
            for (int fc = 0; fc < NFRAG; fc++)
#pragma unroll
                for (int fr = 0; fr < 2; fr++)
                    mma_f16(acc[fr][fc], a[fr], b[fc][0], b[fc][1]);
        }
        __syncthreads();
    }

    // epilogue: bias + float2 stores (C-frag rows g, g+8; cols 2tg, 2tg+1)
#pragma unroll
    for (int fr = 0; fr < 2; fr++) {
        int r0 = bm + wr + fr * 16 + g;
#pragma unroll
        for (int fc = 0; fc < NFRAG; fc++) {
            int c = bn + wc + fc * 8 + tg * 2;
            float2 bb = *(const float2*)(bias + c);
            if (r0 < M) {
                float2 o = make_float2(acc[fr][fc][0] + bb.x, acc[fr][fc][1] + bb.y);
                *(float2*)(C + (size_t)r0 * NC + c) = o;
            }
            if (r0 + 8 < M) {
                float2 o = make_float2(acc[fr][fc][2] + bb.x, acc[fr][fc][3] + bb.y);
                *(float2*)(C + (size_t)(r0 + 8) * NC + c) = o;
            }
        }
    }
}

// ---------------- edge kernels (warp per dst node, online softmax, 1-edge prefetch) ----------------
__device__ __forceinline__ float lrelu(float t) { return t > 0.f ? t : 0.2f * t; }
__device__ __forceinline__ float lrdot(float4 h, float4 d, float4 a) {
    return lrelu(h.x + d.x) * a.x + lrelu(h.y + d.y) * a.y +
           lrelu(h.z + d.z) * a.z + lrelu(h.w + d.w) * a.w;
}

__global__ void __launch_bounds__(256) gat_edge_d64(
    const float* __restrict__ hs, const float* __restrict__ hd,
    const float* __restrict__ attn, const float* __restrict__ res,
    float* __restrict__ xout, __half* __restrict__ xh, int N)
{
    int w = (blockIdx.x * blockDim.x + threadIdx.x) >> 5;
    if (w >= N) return;
    int lane = threadIdx.x & 31;
    int i1 = 4 * lane, i2 = 128 + 4 * lane;
    size_t nb = (size_t)w * 256;
    float4 a1 = *(const float4*)(attn + i1);
    float4 a2 = *(const float4*)(attn + i2);
    float4 d1 = *(const float4*)(hd + nb + i1);
    float4 d2 = *(const float4*)(hd + nb + i2);
    float m1 = -1e30f, s1 = 0.f, m2 = -1e30f, s2 = 0.f;
    float4 c1 = make_float4(0.f, 0.f, 0.f, 0.f);
    float4 c2 = make_float4(0.f, 0.f, 0.f, 0.f);
    int e0 = g_off[w], e1 = g_off[w + 1];
    float4 h1c, h2c;
    if (e0 < e1) {
        const float* hp = hs + (size_t)g_ssrc[e0] * 256;
        h1c = *(const float4*)(hp + i1);
        h2c = *(const float4*)(hp + i2);
    }
    for (int e = e0; e < e1; e++) {
        float4 h1 = h1c, h2 = h2c;
        if (e + 1 < e1) {
            const float* hp = hs + (size_t)g_ssrc[e + 1] * 256;
            h1c = *(const float4*)(hp + i1);
            h2c = *(const float4*)(hp + i2);
        }
        float p1 = lrdot(h1, d1, a1);
        float p2 = lrdot(h2, d2, a2);
#pragma unroll
        for (int o = 8; o; o >>= 1) {
            p1 += __shfl_xor_sync(0xffffffffu, p1, o);
            p2 += __shfl_xor_sync(0xffffffffu, p2, o);
        }
        float nm = fmaxf(m1, p1);
        float sc = __expf(m1 - nm), wt = __expf(p1 - nm);
        s1 = s1 * sc + wt;
        c1.x = c1.x * sc + wt * h1.x; c1.y = c1.y * sc + wt * h1.y;
        c1.z = c1.z * sc + wt * h1.z; c1.w = c1.w * sc + wt * h1.w;
        m1 = nm;
        nm = fmaxf(m2, p2);
        sc = __expf(m2 - nm); wt = __expf(p2 - nm);
        s2 = s2 * sc + wt;
        c2.x = c2.x * sc + wt * h2.x; c2.y = c2.y * sc + wt * h2.y;
        c2.z = c2.z * sc + wt * h2.z; c2.w = c2.w * sc + wt * h2.w;
        m2 = nm;
    }
    float v1 = (s1 > 0.f) ? 1.f / s1 : 0.f;
    float v2 = (s2 > 0.f) ? 1.f / s2 : 0.f;
    float4 r1 = *(const float4*)(res + nb + i1);
    float4 r2 = *(const float4*)(res + nb + i2);
    float o1[4], o2[4];
    o1[0] = c1.x * v1 + r1.x; o1[1] = c1.y * v1 + r1.y;
    o1[2] = c1.z * v1 + r1.z; o1[3] = c1.w * v1 + r1.w;
    o2[0] = c2.x * v2 + r2.x; o2[1] = c2.y * v2 + r2.y;
    o2[2] = c2.z * v2 + r2.z; o2[3] = c2.w * v2 + r2.w;
    if (xout) {
        *(float4*)(xout + nb + i1) = make_float4(o1[0], o1[1], o1[2], o1[3]);
        *(float4*)(xout + nb + i2) = make_float4(o2[0], o2[1], o2[2], o2[3]);
    }
    __half2* xh2 = (__half2*)(xh + nb);
#pragma unroll
    for (int j = 0; j < 2; j++) {
        xh2[(i1 >> 1) + j] = __floats2half2_rn(o1[2*j], o1[2*j+1]);
        xh2[(i2 >> 1) + j] = __floats2half2_rn(o2[2*j], o2[2*j+1]);
    }
}

__global__ void __launch_bounds__(256) gat_edge_d40(
    const float* __restrict__ hs, const float* __restrict__ hd,
    const float* __restrict__ attn, const float* __restrict__ res,
    float* __restrict__ out, int N)
{
    int w = (blockIdx.x * blockDim.x + threadIdx.x) >> 5;
    if (w >= N) return;
    int lane = threadIdx.x & 31;
    int h = lane >> 3;
    int d0 = (lane & 7) * 5;
    int idx = h * 40 + d0;
    float a[5], dv[5];
#pragma unroll
    for (int j = 0; j < 5; j++) {
        a[j] = attn[idx + j];
        dv[j] = hd[(size_t)w * 160 + idx + j];
    }
    float m = -1e30f, s = 0.f;
    float acc[5] = {0.f, 0.f, 0.f, 0.f, 0.f};
    int e0 = g_off[w], e1 = g_off[w + 1];
    float hc[5];
    if (e0 < e1) {
        const float* hp = hs + (size_t)g_ssrc[e0] * 160 + idx;
#pragma unroll
        for (int j = 0; j < 5; j++) hc[j] = hp[j];
    }
    for (int e = e0; e < e1; e++) {
        float hv[5];
#pragma unroll
        for (int j = 0; j < 5; j++) hv[j] = hc[j];
        if (e + 1 < e1) {
            const float* hp = hs + (size_t)g_ssrc[e + 1] * 160 + idx;
#pragma unroll
            for (int j = 0; j < 5; j++) hc[j] = hp[j];
        }
        float p = 0.f;
#pragma unroll
        for (int j = 0; j < 5; j++) p += lrelu(hv[j] + dv[j]) * a[j];
#pragma unroll
        for (int o = 4; o; o >>= 1) p += __shfl_xor_sync(0xffffffffu, p, o);
        float nm = fmaxf(m, p);
        float sc = __expf(m - nm), wt = __expf(p - nm);
        s = s * sc + wt;
#pragma unroll
        for (int j = 0; j < 5; j++) acc[j] = acc[j] * sc + wt * hv[j];
        m = nm;
    }
    float inv = (s > 0.f) ? 1.f / s : 0.f;
    float v[5];
#pragma unroll
    for (int j = 0; j < 5; j++) v[j] = acc[j] * inv + res[(size_t)w * 160 + idx + j];
#pragma unroll
    for (int j = 0; j < 5; j++) {
        v[j] += __shfl_xor_sync(0xffffffffu, v[j], 8);
        v[j] += __shfl_xor_sync(0xffffffffu, v[j], 16);
    }
    if (lane < 8) {
#pragma unroll
        for (int j = 0; j < 5; j++) out[(size_t)w * 40 + d0 + j] = 0.25f * v[j];
    }
}

// ---------------- launch ----------------
#define SMEM_G4 (2 * (128 * 80 + 128 * 80))   // 40960
#define SMEM_G5 (2 * (128 * 80 + 160 * 80))   // 46080

extern "C" void kernel_launch(void* const* d_in, const int* in_sizes, int n_in,
                              void* d_out, int out_size)
{
    const float* x0  = (const float*)d_in[0];
    const int*   src = (const int*)d_in[1];
    const int*   dst = (const int*)d_in[2];
    const float* ws0 = (const float*)d_in[3];
    const float* bs0 = (const float*)d_in[4];
    const float* wd0 = (const float*)d_in[5];
    const float* bd0 = (const float*)d_in[6];
    const float* at0 = (const float*)d_in[7];
    const float* wr0 = (const float*)d_in[8];
    const float* br0 = (const float*)d_in[9];
    const float* ws1 = (const float*)d_in[10];
    const float* bs1 = (const float*)d_in[11];
    const float* wd1 = (const float*)d_in[12];
    const float* bd1 = (const float*)d_in[13];
    const float* at1 = (const float*)d_in[14];
    const float* ws2 = (const float*)d_in[15];
    const float* bs2 = (const float*)d_in[16];
    const float* wd2 = (const float*)d_in[17];
    const float* bd2 = (const float*)d_in[18];
    const float* at2 = (const float*)d_in[19];
    const float* wr2 = (const float*)d_in[20];
    const float* br2 = (const float*)d_in[21];
    float* out = (float*)d_out;

    const int N = NN, E = EE;

    float *hs, *hd, *res, *xA;
    __half *xh, *wh;
    cudaGetSymbolAddress((void**)&hs,  g_hs);
    cudaGetSymbolAddress((void**)&hd,  g_hd);
    cudaGetSymbolAddress((void**)&res, g_res);
    cudaGetSymbolAddress((void**)&xA,  g_xA);
    cudaGetSymbolAddress((void**)&xh,  g_xh);
    cudaGetSymbolAddress((void**)&wh,  g_wh);

    cudaFuncSetAttribute(gemm_f16<4>, cudaFuncAttributeMaxDynamicSharedMemorySize, SMEM_G4);
    cudaFuncSetAttribute(gemm_f16<5>, cudaFuncAttributeMaxDynamicSharedMemorySize, SMEM_G5);

    const int MB = (N + 127) / 128;
    const int ewarps = (N * 32 + 255) / 256;
    const dim3 g2(MB, 2);

    // ---- layer 0 prep + GEMMs first (so ncu -s 5 -c 1 lands on a GEMM) ----
    k_xcvt<<<(N * 128 + 255) / 256, 256>>>(x0, xh, N * 128);
    k_wcvt<<<(128 * 256 + 255) / 256, 256>>>(ws0, 128, 256, WOFF_S0);
    k_wcvt<<<(128 * 256 + 255) / 256, 256>>>(wd0, 128, 256, WOFF_D0);
    gemm_f16<4><<<g2, 512, SMEM_G4>>>(xh, wh, WOFF_S0, bs0, hs, N, 128, 256);
    gemm_f16<4><<<g2, 512, SMEM_G4>>>(xh, wh, WOFF_D0, bd0, hd, N, 128, 256);
    k_wcvt<<<(128 * 256 + 255) / 256, 256>>>(wr0, 128, 256, WOFF_R0);
    gemm_f16<4><<<g2, 512, SMEM_G4>>>(xh, wh, WOFF_R0, br0, res, N, 128, 256);

    // ---- CSR by dst (needed before first edge kernel) ----
    k_zero<<<(N + 255) / 256, 256>>>(N);
    k_hist<<<(E + 255) / 256, 256>>>(dst, E);
    int NB = (N + 1023) / 1024;
    k_scan_reduce<<<NB, 1024>>>(N);
    k_scan_bsum<<<1, 1>>>(NB, N, E);
    k_scan_final<<<NB, 1024>>>(N);
    k_scatter<<<(E + 255) / 256, 256>>>(src, dst, E);

    gat_edge_d64<<<ewarps, 256>>>(hs, hd, at0, res, xA, xh, N);

    // ---- layer 1: K=256, NC=256, identity residual ----
    k_wcvt<<<(256 * 256 + 255) / 256, 256>>>(ws1, 256, 256, WOFF_S1);
    k_wcvt<<<(256 * 256 + 255) / 256, 256>>>(wd1, 256, 256, WOFF_D1);
    gemm_f16<4><<<g2, 512, SMEM_G4>>>(xh, wh, WOFF_S1, bs1, hs, N, 256, 256);
    gemm_f16<4><<<g2, 512, SMEM_G4>>>(xh, wh, WOFF_D1, bd1, hd, N, 256, 256);
    gat_edge_d64<<<ewarps, 256>>>(hs, hd, at1, xA, nullptr, xh, N);

    // ---- layer 2: K=256, NC=160 (BN=160, no padding), fused head-mean ----
    k_wcvt<<<(256 * 160 + 255) / 256, 256>>>(ws2, 256, 160, WOFF_S2);
    k_wcvt<<<(256 * 160 + 255) / 256, 256>>>(wd2, 256, 160, WOFF_D2);
    k_wcvt<<<(256 * 160 + 255) / 256, 256>>>(wr2, 256, 160, WOFF_R2);
    gemm_f16<5><<<MB, 512, SMEM_G5>>>(xh, wh, WOFF_S2, bs2, hs, N, 256, 160);
    gemm_f16<5><<<MB, 512, SMEM_G5>>>(xh, wh, WOFF_D2, bd2, hd, N, 256, 160);
    gemm_f16<5><<<MB, 512, SMEM_G5>>>(xh, wh, WOFF_R2, br2, res, N, 256, 160);
    gat_edge_d40<<<ewarps, 256>>>(hs, hd, at2, res, out, N);
}